// round 4
// baseline (speedup 1.0000x reference)
#include <cuda_runtime.h>
#include <cuda_bf16.h>
#include <cstdint>

#define BATCH   8192
#define DIM     1024
#define HALF_B  4096

// ---------------- device scratch (static, no runtime alloc) ----------------
__device__ uint8_t g_P[2][BATCH][DIM];         // permuted, normalized, e4m3, scaled x16 (16 MB)
__device__ int   g_perm[BATCH];
__device__ float g_S[2][2][BATCH];             // [same=0/cross=1][feature][row]

// ---------------- helpers ----------------
__device__ __forceinline__ uint32_t smem_u32(const void* p) {
    uint32_t a;
    asm("{ .reg .u64 t; cvta.to.shared.u64 t, %1; cvt.u32.u64 %0, t; }" : "=r"(a) : "l"(p));
    return a;
}
__device__ __forceinline__ void cpa16(uint32_t s, const void* g) {
    asm volatile("cp.async.cg.shared.global [%0], [%1], 16;" :: "r"(s), "l"(g) : "memory");
}
#define SWZ(o) ((o) ^ (((o) >> 3) & 0x70))

__device__ __forceinline__ void ldmatrix_x4(uint32_t& r0, uint32_t& r1, uint32_t& r2, uint32_t& r3,
                                            uint32_t addr) {
    asm volatile("ldmatrix.sync.aligned.m8n8.x4.shared.b16 {%0,%1,%2,%3}, [%4];"
                 : "=r"(r0), "=r"(r1), "=r"(r2), "=r"(r3) : "r"(addr));
}
__device__ __forceinline__ void ldmatrix_x2(uint32_t& r0, uint32_t& r1, uint32_t addr) {
    asm volatile("ldmatrix.sync.aligned.m8n8.x2.shared.b16 {%0,%1}, [%2];"
                 : "=r"(r0), "=r"(r1) : "r"(addr));
}
__device__ __forceinline__ void mma_fp8(float* c, const uint32_t* a, const uint32_t* b) {
    asm volatile("mma.sync.aligned.m16n8k32.row.col.f32.e4m3.e4m3.f32 "
                 "{%0,%1,%2,%3}, {%4,%5,%6,%7}, {%8,%9}, {%0,%1,%2,%3};"
                 : "+f"(c[0]), "+f"(c[1]), "+f"(c[2]), "+f"(c[3])
                 : "r"(a[0]), "r"(a[1]), "r"(a[2]), "r"(a[3]), "r"(b[0]), "r"(b[1]));
}
__device__ __forceinline__ uint16_t cvt_e4m3x2(float hi, float lo) {
    uint16_t r;
    asm("cvt.rn.satfinite.e4m3x2.f32 %0, %1, %2;" : "=h"(r) : "f"(hi), "f"(lo));
    return r;
}

// ---------------- kernel 1: permutation (stable partition by label) ----------------
__global__ void perm_kernel(const int* __restrict__ label) {
    __shared__ int wsum[32];
    int t = threadIdx.x;
    int l[8]; int c = 0;
#pragma unroll
    for (int i = 0; i < 8; i++) { l[i] = label[t * 8 + i]; c += l[i]; }
    int v = c, lane = t & 31, w = t >> 5;
#pragma unroll
    for (int o = 1; o < 32; o <<= 1) {
        int n = __shfl_up_sync(0xffffffffu, v, o);
        if (lane >= o) v += n;
    }
    if (lane == 31) wsum[w] = v;
    __syncthreads();
    if (w == 0) {
        int x = wsum[lane];
#pragma unroll
        for (int o = 1; o < 32; o <<= 1) {
            int n = __shfl_up_sync(0xffffffffu, x, o);
            if (lane >= o) x += n;
        }
        wsum[lane] = x;
    }
    __syncthreads();
    int run = v - c + (w ? wsum[w - 1] : 0);   // ones strictly before t*8
#pragma unroll
    for (int i = 0; i < 8; i++) {
        int idx = t * 8 + i;
        g_perm[idx] = l[i] ? run : (HALF_B + (idx - run));
        run += l[i];
    }
}

// ---------------- kernel 2: normalize + scatter to scaled e4m3 ----------------
// feature scaled by 16 before quantization (keeps e4m3 in normal range);
// Gram acc = 256 * sim, rescaled in the GEMM epilogue.
__global__ void norm_kernel(const float* __restrict__ text, const float* __restrict__ image) {
    int f = blockIdx.y;
    int row = blockIdx.x;
    int t = threadIdx.x;
    const float4* src = (const float4*)((f == 0 ? text : image) + (size_t)row * DIM);
    float4 v = src[t];
    float s = v.x * v.x + v.y * v.y + v.z * v.z + v.w * v.w;
#pragma unroll
    for (int o = 16; o; o >>= 1) s += __shfl_xor_sync(0xffffffffu, s, o);
    __shared__ float ws[8];
    __shared__ float s_inv;
    if ((t & 31) == 0) ws[t >> 5] = s;
    __syncthreads();
    if (t == 0) {
        float a = 0.f;
#pragma unroll
        for (int wq = 0; wq < 8; wq++) a += ws[wq];
        s_inv = 16.0f / fmaxf(sqrtf(a), 1e-12f);
    }
    __syncthreads();
    float inv = s_inv;
    int dest = g_perm[row];
    uint16_t lo = cvt_e4m3x2(v.y * inv, v.x * inv);
    uint16_t hi = cvt_e4m3x2(v.w * inv, v.z * inv);
    ((uint32_t*)&g_P[f][dest][0])[t] = (uint32_t)lo | ((uint32_t)hi << 16);
}

// ---------------- kernel 3: symmetric Gram GEMM (FP8 QMMA) + fused exp-sum epilogue
// 128x128 tile per CTA, only lower-triangular tile pairs (tm >= tn).
// 256 threads = 8 warps; warp tile 64x32 (wm = wid&1 along M, wn = wid>>1 along N).
constexpr int BKB = 128, NCHUNK = DIM / BKB, STAGES = 4;   // 128 bytes = 128 fp8 elems per chunk
constexpr int STAGE_A = 128 * 128;          // 16 KB (128 rows x 128 B)
constexpr int STAGE_BYTES = 2 * STAGE_A;    // 32 KB (A + B)
constexpr int SMEM_DYN = 1024 + STAGES * STAGE_BYTES;      // ~129 KB
constexpr int NTILE = BATCH / 128;          // 64
constexpr int NPAIR = NTILE * (NTILE + 1) / 2;   // 2080

__global__ void __launch_bounds__(256, 1) gram_kernel() {
    extern __shared__ char smem_raw[];
    uint32_t sb = (smem_u32(smem_raw) + 1023u) & ~1023u;   // 1KB-align for SW128 banking
    int tid = threadIdx.x, lane = tid & 31, wid = tid >> 5;
    int p = blockIdx.x, f = blockIdx.y;

    // triangular decode: tm >= tn
    int tm = (int)((sqrtf(8.f * (float)p + 1.f) - 1.f) * 0.5f);
    while ((tm + 1) * (tm + 2) / 2 <= p) tm++;
    while (tm * (tm + 1) / 2 > p) tm--;
    int tn = p - tm * (tm + 1) / 2;
    bool diag = (tm == tn);

    const char* baseA = (const char*)&g_P[f][tm * 128][0];
    const char* baseB = (const char*)&g_P[f][tn * 128][0];

    auto load_chunk = [&](int c, int s) {
        uint32_t dA = sb + s * STAGE_BYTES;
        uint32_t dB = dA + STAGE_A;
        const char* gA = baseA + c * BKB;
        const char* gB = baseB + c * BKB;
#pragma unroll
        for (int i = 0; i < 4; i++) {       // A: 128 rows x 8 segs of 16B = 1024 cp / 256 thr
            int o = tid + (i << 8); int r = o >> 3, sg = o & 7;
            cpa16(dA + SWZ(r * 128 + sg * 16), gA + (size_t)r * DIM + sg * 16);
        }
#pragma unroll
        for (int i = 0; i < 4; i++) {
            int o = tid + (i << 8); int r = o >> 3, sg = o & 7;
            cpa16(dB + SWZ(r * 128 + sg * 16), gB + (size_t)r * DIM + sg * 16);
        }
        asm volatile("cp.async.commit_group;" ::: "memory");
    };

    // prologue: fill 3 of 4 stages (one stage always idle -> single barrier/iter suffices)
    for (int c = 0; c < STAGES - 1; c++) load_chunk(c, c);

    int wm = wid & 1, wn = wid >> 1;
    int rWarp = wm * 64;            // warp's M offset within tile
    int cWarp = wn * 32;            // warp's N offset within tile
    int quad = lane >> 3, laneRow = lane & 7;
    // fp8 m16n8k32 fragments via b16 ldmatrix: same byte addressing pattern as bf16
    int aRowOff = rWarp + (quad & 1) * 8 + laneRow;   // + mi*16
    int aByteOff = (quad >> 1) * 16;                  // + ks*32 (bytes)
    int bRowOff = cWarp + laneRow;                    // + ni*8
    int bByteOff = ((lane >> 3) & 1) * 16;            // + ks*32 (bytes)

    float acc[4][4][4];
#pragma unroll
    for (int mi = 0; mi < 4; mi++)
#pragma unroll
        for (int ni = 0; ni < 4; ni++)
#pragma unroll
            for (int j = 0; j < 4; j++) acc[mi][ni][j] = 0.f;

    for (int c = 0; c < NCHUNK; c++) {
        int s = c & (STAGES - 1);
        asm volatile("cp.async.wait_group 2;" ::: "memory");
        __syncthreads();   // separates prev-iter reads of stage (c+3)%4 from this iter's writes
        uint32_t dA = sb + s * STAGE_BYTES;
        uint32_t dB = dA + STAGE_A;
#pragma unroll
        for (int ks = 0; ks < 4; ks++) {   // 4 k-steps of 32 fp8 elements each
            uint32_t a[4][4], b[4][2];
#pragma unroll
            for (int mi = 0; mi < 4; mi++)
                ldmatrix_x4(a[mi][0], a[mi][1], a[mi][2], a[mi][3],
                            dA + SWZ((aRowOff + mi * 16) * 128 + ks * 32 + aByteOff));
#pragma unroll
            for (int ni = 0; ni < 4; ni++)
                ldmatrix_x2(b[ni][0], b[ni][1],
                            dB + SWZ((bRowOff + ni * 8) * 128 + ks * 32 + bByteOff));
#pragma unroll
            for (int mi = 0; mi < 4; mi++)
#pragma unroll
                for (int ni = 0; ni < 4; ni++)
                    mma_fp8(acc[mi][ni], a[mi], b[ni]);
        }
        if (c + STAGES - 1 < NCHUNK) load_chunk(c + STAGES - 1, (c + STAGES - 1) & (STAGES - 1));
        else asm volatile("cp.async.commit_group;" ::: "memory");  // keep group accounting aligned
    }

    // ---- epilogue: exp(2*sim) = exp(acc/128), row sums (and col sums via symmetry) ----
    constexpr float ESC = 1.0f / 128.0f;   // 2 / (16*16)
    int rBase = tm * 128 + rWarp;
    int cBase = tn * 128 + cWarp;
    int sc = ((tm < (NTILE / 2)) == (tn < (NTILE / 2))) ? 0 : 1;

    float rsum[4][2];
    float csum[4][2];
#pragma unroll
    for (int i = 0; i < 4; i++) { rsum[i][0] = rsum[i][1] = 0.f; csum[i][0] = csum[i][1] = 0.f; }

#pragma unroll
    for (int mi = 0; mi < 4; mi++) {
        int grow0 = rBase + mi * 16 + (lane >> 2);
        int grow1 = grow0 + 8;
#pragma unroll
        for (int ni = 0; ni < 4; ni++) {
            int gc = cBase + ni * 8 + 2 * (lane & 3);
            float e0 = __expf(ESC * acc[mi][ni][0]);
            float e1 = __expf(ESC * acc[mi][ni][1]);
            float e2 = __expf(ESC * acc[mi][ni][2]);
            float e3 = __expf(ESC * acc[mi][ni][3]);
            if (diag) {
                if (grow0 == gc)     e0 = 0.f;
                if (grow0 == gc + 1) e1 = 0.f;
                if (grow1 == gc)     e2 = 0.f;
                if (grow1 == gc + 1) e3 = 0.f;
            }
            rsum[mi][0] += e0 + e1;
            rsum[mi][1] += e2 + e3;
            csum[ni][0] += e0 + e2;
            csum[ni][1] += e1 + e3;
        }
    }

    // row sums: reduce across lanes sharing a row (lane&3 varies -> xor 1,2)
#pragma unroll
    for (int mi = 0; mi < 4; mi++) {
#pragma unroll
        for (int j = 0; j < 2; j++) {
            float v = rsum[mi][j];
            v += __shfl_xor_sync(0xffffffffu, v, 1);
            v += __shfl_xor_sync(0xffffffffu, v, 2);
            if ((lane & 3) == 0) {
                int grow = rBase + mi * 16 + (lane >> 2) + j * 8;
                atomicAdd(&g_S[sc][f][grow], v);
            }
        }
    }

    // col sums (symmetric contribution) only for off-diagonal tiles:
    if (!diag) {
#pragma unroll
        for (int ni = 0; ni < 4; ni++) {
#pragma unroll
            for (int j = 0; j < 2; j++) {
                float v = csum[ni][j];
                v += __shfl_xor_sync(0xffffffffu, v, 4);
                v += __shfl_xor_sync(0xffffffffu, v, 8);
                v += __shfl_xor_sync(0xffffffffu, v, 16);
                if (lane < 4) {
                    int gc = cBase + ni * 8 + 2 * lane + j;
                    atomicAdd(&g_S[sc][f][gc], v);
                }
            }
        }
    }
}

// ---------------- kernel 4: final loss reduction (1024 thr, 16 independent elems each) ----
__global__ void loss_kernel(float* __restrict__ out) {
    __shared__ float ws[32];
    int t = threadIdx.x;
    float nom[16], cr[16];
#pragma unroll
    for (int i = 0; i < 16; i++) {
        int idx = t + i * 1024;
        int f = idx >> 13, r = idx & (BATCH - 1);
        nom[i] = g_S[0][f][r];
        cr[i]  = g_S[1][f][r];
    }
    float p = 0.f;
#pragma unroll
    for (int i = 0; i < 16; i++)
        p += -logf(nom[i] / (nom[i] + cr[i]) + 1e-8f);
#pragma unroll
    for (int o = 16; o; o >>= 1) p += __shfl_xor_sync(0xffffffffu, p, o);
    if ((t & 31) == 0) ws[t >> 5] = p;
    __syncthreads();
    if (t == 0) {
        float a = 0.f;
#pragma unroll
        for (int w = 0; w < 32; w++) a += ws[w];
        out[0] = a * (1.0f / HALF_B);
    }
}

// ---------------- launch ----------------
extern "C" void kernel_launch(void* const* d_in, const int* in_sizes, int n_in,
                              void* d_out, int out_size) {
    const float* text  = (const float*)d_in[0];
    const float* image = (const float*)d_in[1];
    const int*   label = (const int*)d_in[2];

    void* sAddr = nullptr;
    cudaGetSymbolAddress(&sAddr, g_S);
    cudaMemsetAsync(sAddr, 0, sizeof(float) * 2 * 2 * BATCH);

    perm_kernel<<<1, 1024>>>(label);
    norm_kernel<<<dim3(BATCH, 2), 256>>>(text, image);

    cudaFuncSetAttribute(gram_kernel, cudaFuncAttributeMaxDynamicSharedMemorySize, SMEM_DYN);
    gram_kernel<<<dim3(NPAIR, 2), 256, SMEM_DYN>>>();

    loss_kernel<<<1, 1024>>>((float*)d_out);
}

// round 7
// speedup vs baseline: 1.3261x; 1.3261x over previous
#include <cuda_runtime.h>
#include <cuda_bf16.h>
#include <cstdint>

#define BATCH   8192
#define DIM     1024
#define HALF_B  4096

// ---------------- device scratch (static, no runtime alloc) ----------------
__device__ __nv_bfloat16 g_P[2][BATCH][DIM];   // permuted, normalized, bf16 (32 MB)
__device__ int   g_perm[BATCH];
__device__ float g_S[2][2][BATCH];             // [same=0/cross=1][feature][row]

// ---------------- helpers ----------------
__device__ __forceinline__ uint32_t smem_u32(const void* p) {
    uint32_t a;
    asm("{ .reg .u64 t; cvta.to.shared.u64 t, %1; cvt.u32.u64 %0, t; }" : "=r"(a) : "l"(p));
    return a;
}
__device__ __forceinline__ void cpa16(uint32_t s, const void* g) {
    asm volatile("cp.async.cg.shared.global [%0], [%1], 16;" :: "r"(s), "l"(g) : "memory");
}
#define SWZ(o) ((o) ^ (((o) >> 3) & 0x70))

__device__ __forceinline__ void ldmatrix_x4(uint32_t& r0, uint32_t& r1, uint32_t& r2, uint32_t& r3,
                                            uint32_t addr) {
    asm volatile("ldmatrix.sync.aligned.m8n8.x4.shared.b16 {%0,%1,%2,%3}, [%4];"
                 : "=r"(r0), "=r"(r1), "=r"(r2), "=r"(r3) : "r"(addr));
}
__device__ __forceinline__ void ldmatrix_x2(uint32_t& r0, uint32_t& r1, uint32_t addr) {
    asm volatile("ldmatrix.sync.aligned.m8n8.x2.shared.b16 {%0,%1}, [%2];"
                 : "=r"(r0), "=r"(r1) : "r"(addr));
}
__device__ __forceinline__ void mma16816(float* c, const uint32_t* a, const uint32_t* b) {
    asm volatile("mma.sync.aligned.m16n8k16.row.col.f32.bf16.bf16.f32 "
                 "{%0,%1,%2,%3}, {%4,%5,%6,%7}, {%8,%9}, {%0,%1,%2,%3};"
                 : "+f"(c[0]), "+f"(c[1]), "+f"(c[2]), "+f"(c[3])
                 : "r"(a[0]), "r"(a[1]), "r"(a[2]), "r"(a[3]), "r"(b[0]), "r"(b[1]));
}

// ---------------- kernel 1: permutation (stable partition by label) ----------------
__global__ void perm_kernel(const int* __restrict__ label) {
    __shared__ int wsum[32];
    int t = threadIdx.x;
    int l[8]; int c = 0;
#pragma unroll
    for (int i = 0; i < 8; i++) { l[i] = label[t * 8 + i]; c += l[i]; }
    int v = c, lane = t & 31, w = t >> 5;
#pragma unroll
    for (int o = 1; o < 32; o <<= 1) {
        int n = __shfl_up_sync(0xffffffffu, v, o);
        if (lane >= o) v += n;
    }
    if (lane == 31) wsum[w] = v;
    __syncthreads();
    if (w == 0) {
        int x = wsum[lane];
#pragma unroll
        for (int o = 1; o < 32; o <<= 1) {
            int n = __shfl_up_sync(0xffffffffu, x, o);
            if (lane >= o) x += n;
        }
        wsum[lane] = x;
    }
    __syncthreads();
    int run = v - c + (w ? wsum[w - 1] : 0);   // ones strictly before t*8
#pragma unroll
    for (int i = 0; i < 8; i++) {
        int idx = t * 8 + i;
        g_perm[idx] = l[i] ? run : (HALF_B + (idx - run));
        run += l[i];
    }
}

// ---------------- kernel 2: normalize + scatter to bf16 ----------------
__global__ void norm_kernel(const float* __restrict__ text, const float* __restrict__ image) {
    int f = blockIdx.y;
    int row = blockIdx.x;
    int t = threadIdx.x;
    const float4* src = (const float4*)((f == 0 ? text : image) + (size_t)row * DIM);
    float4 v = src[t];
    float s = v.x * v.x + v.y * v.y + v.z * v.z + v.w * v.w;
#pragma unroll
    for (int o = 16; o; o >>= 1) s += __shfl_xor_sync(0xffffffffu, s, o);
    __shared__ float ws[8];
    __shared__ float s_inv;
    if ((t & 31) == 0) ws[t >> 5] = s;
    __syncthreads();
    if (t == 0) {
        float a = 0.f;
#pragma unroll
        for (int wq = 0; wq < 8; wq++) a += ws[wq];
        s_inv = 1.0f / fmaxf(sqrtf(a), 1e-12f);
    }
    __syncthreads();
    float inv = s_inv;
    int dest = g_perm[row];
    __nv_bfloat16* dst = &g_P[f][dest][0];
    __nv_bfloat162 a0 = __floats2bfloat162_rn(v.x * inv, v.y * inv);
    __nv_bfloat162 a1 = __floats2bfloat162_rn(v.z * inv, v.w * inv);
    ((__nv_bfloat162*)dst)[2 * t]     = a0;
    ((__nv_bfloat162*)dst)[2 * t + 1] = a1;
}

// ---------------- dummy kernels (shift ncu -s 5 window onto gram_kernel) ------------
__global__ void dummy_kernel() {}

// ---------------- kernel 3: symmetric Gram GEMM (HMMA) + fused exp-sum epilogue ----
// 128x128 tile per CTA, only lower-triangular tile pairs (tm >= tn).
// 128 threads = 4 warps; warp tile 64x64 (wm = wid&1 along M, wn = wid>>1 along N).
// 2 CTAs co-resident per SM hide barriers/prologue/epilogue.
constexpr int NCHUNK = DIM / 64, STAGES = 3;
constexpr int STAGE_A = 128 * 128;          // 16 KB (128 rows x 64 bf16)
constexpr int STAGE_BYTES = 2 * STAGE_A;    // 32 KB (A + B)
constexpr int SMEM_DYN = STAGES * STAGE_BYTES;   // 96 KB (1KB-aligned by attribute)
constexpr int NTILE = BATCH / 128;          // 64
constexpr int NPAIR = NTILE * (NTILE + 1) / 2;   // 2080

__global__ void __launch_bounds__(128, 2) gram_kernel() {
    extern __shared__ __align__(1024) char smem_raw[];
    uint32_t sb = smem_u32(smem_raw);
    int tid = threadIdx.x, lane = tid & 31, wid = tid >> 5;
    int p = blockIdx.x, f = blockIdx.y;

    // triangular decode: tm >= tn
    int tm = (int)((sqrtf(8.f * (float)p + 1.f) - 1.f) * 0.5f);
    while ((tm + 1) * (tm + 2) / 2 <= p) tm++;
    while (tm * (tm + 1) / 2 > p) tm--;
    int tn = p - tm * (tm + 1) / 2;
    bool diag = (tm == tn);

    const char* baseA = (const char*)&g_P[f][tm * 128][0];
    const char* baseB = (const char*)&g_P[f][tn * 128][0];

    auto load_chunk = [&](int c, int s) {
        uint32_t dA = sb + s * STAGE_BYTES;
        uint32_t dB = dA + STAGE_A;
        const char* gA = baseA + c * 128;
        const char* gB = baseB + c * 128;
#pragma unroll
        for (int i = 0; i < 8; i++) {       // A: 128 rows x 8 segs = 1024 cp / 128 thr
            int o = tid + (i << 7); int r = o >> 3, sg = o & 7;
            cpa16(dA + SWZ(r * 128 + sg * 16), gA + (size_t)r * 2048 + sg * 16);
        }
#pragma unroll
        for (int i = 0; i < 8; i++) {
            int o = tid + (i << 7); int r = o >> 3, sg = o & 7;
            cpa16(dB + SWZ(r * 128 + sg * 16), gB + (size_t)r * 2048 + sg * 16);
        }
        asm volatile("cp.async.commit_group;" ::: "memory");
    };

    for (int c = 0; c < STAGES; c++) load_chunk(c, c);

    int wm = wid & 1, wn = wid >> 1;
    int rWarp = wm * 64;            // warp's M offset within tile
    int cWarp = wn * 64;            // warp's N offset within tile
    int quad = lane >> 3, laneRow = lane & 7;
    int aRowOff = rWarp + (quad & 1) * 8 + laneRow;   // + mi*16
    int aColOff = (quad >> 1) * 8;                    // + ks*16
    int bRowOff = cWarp + laneRow;                    // + ni*8
    int bColOff = ((lane >> 3) & 1) * 8;              // + ks*16

    float acc[4][8][4];
#pragma unroll
    for (int mi = 0; mi < 4; mi++)
#pragma unroll
        for (int ni = 0; ni < 8; ni++)
#pragma unroll
            for (int j = 0; j < 4; j++) acc[mi][ni][j] = 0.f;

    for (int c = 0; c < NCHUNK; c++) {
        int s = c % STAGES;
        asm volatile("cp.async.wait_group 2;" ::: "memory");
        __syncthreads();
        uint32_t dA = sb + s * STAGE_BYTES;
        uint32_t dB = dA + STAGE_A;
#pragma unroll
        for (int ks = 0; ks < 4; ks++) {
            uint32_t a[4][4], b[8][2];
#pragma unroll
            for (int mi = 0; mi < 4; mi++)
                ldmatrix_x4(a[mi][0], a[mi][1], a[mi][2], a[mi][3],
                            dA + SWZ((aRowOff + mi * 16) * 128 + (ks * 16 + aColOff) * 2));
#pragma unroll
            for (int ni = 0; ni < 8; ni++)
                ldmatrix_x2(b[ni][0], b[ni][1],
                            dB + SWZ((bRowOff + ni * 8) * 128 + (ks * 16 + bColOff) * 2));
#pragma unroll
            for (int mi = 0; mi < 4; mi++)
#pragma unroll
                for (int ni = 0; ni < 8; ni++)
                    mma16816(acc[mi][ni], a[mi], b[ni]);
        }
        __syncthreads();   // all warps done reading stage s before overwrite
        if (c + STAGES < NCHUNK) load_chunk(c + STAGES, s);
        else asm volatile("cp.async.commit_group;" ::: "memory");
    }

    // ---- epilogue: exp(2*sim), row sums (and col sums via symmetry) ----
    int rBase = tm * 128 + rWarp;
    int cBase = tn * 128 + cWarp;
    int sc = ((tm < (NTILE / 2)) == (tn < (NTILE / 2))) ? 0 : 1;

    float rsum[4][2];
    float csum[8][2];
#pragma unroll
    for (int i = 0; i < 4; i++) { rsum[i][0] = rsum[i][1] = 0.f; }
#pragma unroll
    for (int i = 0; i < 8; i++) { csum[i][0] = csum[i][1] = 0.f; }

#pragma unroll
    for (int mi = 0; mi < 4; mi++) {
        int grow0 = rBase + mi * 16 + (lane >> 2);
        int grow1 = grow0 + 8;
#pragma unroll
        for (int ni = 0; ni < 8; ni++) {
            int gc = cBase + ni * 8 + 2 * (lane & 3);
            float e0 = __expf(2.f * acc[mi][ni][0]);
            float e1 = __expf(2.f * acc[mi][ni][1]);
            float e2 = __expf(2.f * acc[mi][ni][2]);
            float e3 = __expf(2.f * acc[mi][ni][3]);
            if (diag) {
                if (grow0 == gc)     e0 = 0.f;
                if (grow0 == gc + 1) e1 = 0.f;
                if (grow1 == gc)     e2 = 0.f;
                if (grow1 == gc + 1) e3 = 0.f;
            }
            rsum[mi][0] += e0 + e1;
            rsum[mi][1] += e2 + e3;
            csum[ni][0] += e0 + e2;
            csum[ni][1] += e1 + e3;
        }
    }

    // row sums: reduce across lanes sharing a row (lane&3 varies -> xor 1,2)
#pragma unroll
    for (int mi = 0; mi < 4; mi++) {
#pragma unroll
        for (int j = 0; j < 2; j++) {
            float v = rsum[mi][j];
            v += __shfl_xor_sync(0xffffffffu, v, 1);
            v += __shfl_xor_sync(0xffffffffu, v, 2);
            if ((lane & 3) == 0) {
                int grow = rBase + mi * 16 + (lane >> 2) + j * 8;
                atomicAdd(&g_S[sc][f][grow], v);
            }
        }
    }

    // col sums (symmetric contribution) only for off-diagonal tiles:
    if (!diag) {
#pragma unroll
        for (int ni = 0; ni < 8; ni++) {
#pragma unroll
            for (int j = 0; j < 2; j++) {
                float v = csum[ni][j];
                v += __shfl_xor_sync(0xffffffffu, v, 4);
                v += __shfl_xor_sync(0xffffffffu, v, 8);
                v += __shfl_xor_sync(0xffffffffu, v, 16);
                if (lane < 4) {
                    int gc = cBase + ni * 8 + 2 * lane + j;
                    atomicAdd(&g_S[sc][f][gc], v);
                }
            }
        }
    }
}

// ---------------- kernel 4: final loss reduction (1024 thr, 16 independent elems each) ----
__global__ void loss_kernel(float* __restrict__ out) {
    __shared__ float ws[32];
    int t = threadIdx.x;
    float nom[16], cr[16];
#pragma unroll
    for (int i = 0; i < 16; i++) {
        int idx = t + i * 1024;
        int f = idx >> 13, r = idx & (BATCH - 1);
        nom[i] = g_S[0][f][r];
        cr[i]  = g_S[1][f][r];
    }
    float p = 0.f;
#pragma unroll
    for (int i = 0; i < 16; i++)
        p += -logf(nom[i] / (nom[i] + cr[i]) + 1e-8f);
#pragma unroll
    for (int o = 16; o; o >>= 1) p += __shfl_xor_sync(0xffffffffu, p, o);
    if ((t & 31) == 0) ws[t >> 5] = p;
    __syncthreads();
    if (t == 0) {
        float a = 0.f;
#pragma unroll
        for (int w = 0; w < 32; w++) a += ws[w];
        out[0] = a * (1.0f / HALF_B);
    }
}

// ---------------- launch ----------------
extern "C" void kernel_launch(void* const* d_in, const int* in_sizes, int n_in,
                              void* d_out, int out_size) {
    const float* text  = (const float*)d_in[0];
    const float* image = (const float*)d_in[1];
    const int*   label = (const int*)d_in[2];

    void* sAddr = nullptr;
    cudaGetSymbolAddress(&sAddr, g_S);
    cudaMemsetAsync(sAddr, 0, sizeof(float) * 2 * 2 * BATCH);   // launch 1

    perm_kernel<<<1, 1024>>>(label);                            // launch 2
    norm_kernel<<<dim3(BATCH, 2), 256>>>(text, image);          // launch 3
    dummy_kernel<<<1, 32>>>();                                  // launch 4
    dummy_kernel<<<1, 32>>>();                                  // launch 5

    cudaFuncSetAttribute(gram_kernel, cudaFuncAttributeMaxDynamicSharedMemorySize, SMEM_DYN);
    gram_kernel<<<dim3(NPAIR, 2), 128, SMEM_DYN>>>();           // launch 6 (ncu -s 5 lands here)

    loss_kernel<<<1, 1024>>>((float*)d_out);                    // launch 7
}

// round 8
// speedup vs baseline: 1.3879x; 1.0466x over previous
#include <cuda_runtime.h>
#include <cuda_bf16.h>
#include <cstdint>

#define BATCH   8192
#define DIM     1024
#define HALF_B  4096

// ---------------- device scratch (static, no runtime alloc) ----------------
__device__ __nv_bfloat16 g_P[2][BATCH][DIM];   // permuted, normalized, bf16 (32 MB)
__device__ int   g_perm[BATCH];
__device__ float g_S[2][2][BATCH];             // [same=0/cross=1][feature][row]

// ---------------- helpers ----------------
__device__ __forceinline__ uint32_t smem_u32(const void* p) {
    uint32_t a;
    asm("{ .reg .u64 t; cvta.to.shared.u64 t, %1; cvt.u32.u64 %0, t; }" : "=r"(a) : "l"(p));
    return a;
}
__device__ __forceinline__ void cpa16(uint32_t s, const void* g) {
    asm volatile("cp.async.cg.shared.global [%0], [%1], 16;" :: "r"(s), "l"(g) : "memory");
}
#define SWZ(o) ((o) ^ (((o) >> 3) & 0x70))

__device__ __forceinline__ void ldmatrix_x4(uint32_t& r0, uint32_t& r1, uint32_t& r2, uint32_t& r3,
                                            uint32_t addr) {
    asm volatile("ldmatrix.sync.aligned.m8n8.x4.shared.b16 {%0,%1,%2,%3}, [%4];"
                 : "=r"(r0), "=r"(r1), "=r"(r2), "=r"(r3) : "r"(addr));
}
__device__ __forceinline__ void ldmatrix_x2(uint32_t& r0, uint32_t& r1, uint32_t addr) {
    asm volatile("ldmatrix.sync.aligned.m8n8.x2.shared.b16 {%0,%1}, [%2];"
                 : "=r"(r0), "=r"(r1) : "r"(addr));
}
__device__ __forceinline__ void mma16816(float* c, const uint32_t* a, const uint32_t* b) {
    asm volatile("mma.sync.aligned.m16n8k16.row.col.f32.bf16.bf16.f32 "
                 "{%0,%1,%2,%3}, {%4,%5,%6,%7}, {%8,%9}, {%0,%1,%2,%3};"
                 : "+f"(c[0]), "+f"(c[1]), "+f"(c[2]), "+f"(c[3])
                 : "r"(a[0]), "r"(a[1]), "r"(a[2]), "r"(a[3]), "r"(b[0]), "r"(b[1]));
}

// ---------------- kernel 1: permutation (stable partition by label) ----------------
__global__ void perm_kernel(const int* __restrict__ label) {
    __shared__ int wsum[32];
    int t = threadIdx.x;
    int l[8]; int c = 0;
#pragma unroll
    for (int i = 0; i < 8; i++) { l[i] = label[t * 8 + i]; c += l[i]; }
    int v = c, lane = t & 31, w = t >> 5;
#pragma unroll
    for (int o = 1; o < 32; o <<= 1) {
        int n = __shfl_up_sync(0xffffffffu, v, o);
        if (lane >= o) v += n;
    }
    if (lane == 31) wsum[w] = v;
    __syncthreads();
    if (w == 0) {
        int x = wsum[lane];
#pragma unroll
        for (int o = 1; o < 32; o <<= 1) {
            int n = __shfl_up_sync(0xffffffffu, x, o);
            if (lane >= o) x += n;
        }
        wsum[lane] = x;
    }
    __syncthreads();
    int run = v - c + (w ? wsum[w - 1] : 0);   // ones strictly before t*8
#pragma unroll
    for (int i = 0; i < 8; i++) {
        int idx = t * 8 + i;
        g_perm[idx] = l[i] ? run : (HALF_B + (idx - run));
        run += l[i];
    }
}

// ---------------- kernel 2: normalize + scatter to bf16 ----------------
__global__ void norm_kernel(const float* __restrict__ text, const float* __restrict__ image) {
    int f = blockIdx.y;
    int row = blockIdx.x;
    int t = threadIdx.x;
    const float4* src = (const float4*)((f == 0 ? text : image) + (size_t)row * DIM);
    float4 v = src[t];
    float s = v.x * v.x + v.y * v.y + v.z * v.z + v.w * v.w;
#pragma unroll
    for (int o = 16; o; o >>= 1) s += __shfl_xor_sync(0xffffffffu, s, o);
    __shared__ float ws[8];
    __shared__ float s_inv;
    if ((t & 31) == 0) ws[t >> 5] = s;
    __syncthreads();
    if (t == 0) {
        float a = 0.f;
#pragma unroll
        for (int wq = 0; wq < 8; wq++) a += ws[wq];
        s_inv = 1.0f / fmaxf(sqrtf(a), 1e-12f);
    }
    __syncthreads();
    float inv = s_inv;
    int dest = g_perm[row];
    __nv_bfloat16* dst = &g_P[f][dest][0];
    __nv_bfloat162 a0 = __floats2bfloat162_rn(v.x * inv, v.y * inv);
    __nv_bfloat162 a1 = __floats2bfloat162_rn(v.z * inv, v.w * inv);
    ((__nv_bfloat162*)dst)[2 * t]     = a0;
    ((__nv_bfloat162*)dst)[2 * t + 1] = a1;
}

// ---------------- dummy kernel (aligns ncu capture window onto gram_kernel) --------
__global__ void dummy_kernel() {}

// ---------------- kernel 3: symmetric Gram GEMM (HMMA) + fused exp-sum epilogue ----
// 128x128 tile per CTA, only lower-triangular tile pairs (tm >= tn).
// 128 threads = 4 warps; warp tile 64x64. 2 CTAs/SM hide barriers/prologue/epilogue.
// Fragment double-buffering: k-step ks+1 LDSMs issue under ks's 32 HMMAs.
constexpr int NCHUNK = DIM / 64, STAGES = 3;
constexpr int STAGE_A = 128 * 128;          // 16 KB (128 rows x 64 bf16)
constexpr int STAGE_BYTES = 2 * STAGE_A;    // 32 KB (A + B)
constexpr int SMEM_DYN = STAGES * STAGE_BYTES;   // 96 KB
constexpr int NTILE = BATCH / 128;          // 64
constexpr int NPAIR = NTILE * (NTILE + 1) / 2;   // 2080

__global__ void __launch_bounds__(128, 2) gram_kernel() {
    extern __shared__ __align__(1024) char smem_raw[];
    uint32_t sb = smem_u32(smem_raw);
    int tid = threadIdx.x, lane = tid & 31, wid = tid >> 5;
    int p = blockIdx.x, f = blockIdx.y;

    // triangular decode: tm >= tn
    int tm = (int)((sqrtf(8.f * (float)p + 1.f) - 1.f) * 0.5f);
    while ((tm + 1) * (tm + 2) / 2 <= p) tm++;
    while (tm * (tm + 1) / 2 > p) tm--;
    int tn = p - tm * (tm + 1) / 2;
    bool diag = (tm == tn);

    const char* baseA = (const char*)&g_P[f][tm * 128][0];
    const char* baseB = (const char*)&g_P[f][tn * 128][0];

    auto load_chunk = [&](int c, int s) {
        uint32_t dA = sb + s * STAGE_BYTES;
        uint32_t dB = dA + STAGE_A;
        const char* gA = baseA + c * 128;
        const char* gB = baseB + c * 128;
#pragma unroll
        for (int i = 0; i < 8; i++) {       // A: 128 rows x 8 segs = 1024 cp / 128 thr
            int o = tid + (i << 7); int r = o >> 3, sg = o & 7;
            cpa16(dA + SWZ(r * 128 + sg * 16), gA + (size_t)r * 2048 + sg * 16);
        }
#pragma unroll
        for (int i = 0; i < 8; i++) {
            int o = tid + (i << 7); int r = o >> 3, sg = o & 7;
            cpa16(dB + SWZ(r * 128 + sg * 16), gB + (size_t)r * 2048 + sg * 16);
        }
        asm volatile("cp.async.commit_group;" ::: "memory");
    };

    for (int c = 0; c < STAGES; c++) load_chunk(c, c);

    int wm = wid & 1, wn = wid >> 1;
    int rWarp = wm * 64;            // warp's M offset within tile
    int cWarp = wn * 64;            // warp's N offset within tile
    int quad = lane >> 3, laneRow = lane & 7;
    int aRowOff = rWarp + (quad & 1) * 8 + laneRow;   // + mi*16
    int aColOff = (quad >> 1) * 8;                    // + ks*16
    int bRowOff = cWarp + laneRow;                    // + ni*8
    int bColOff = ((lane >> 3) & 1) * 8;              // + ks*16

    float acc[4][8][4];
#pragma unroll
    for (int mi = 0; mi < 4; mi++)
#pragma unroll
        for (int ni = 0; ni < 8; ni++)
#pragma unroll
            for (int j = 0; j < 4; j++) acc[mi][ni][j] = 0.f;

    uint32_t af[2][4][4], bf[2][8][2];

    for (int c = 0; c < NCHUNK; c++) {
        int s = c % STAGES;
        asm volatile("cp.async.wait_group 2;" ::: "memory");
        __syncthreads();
        uint32_t dA = sb + s * STAGE_BYTES;
        uint32_t dB = dA + STAGE_A;

        // prime k-step 0 fragments
#pragma unroll
        for (int mi = 0; mi < 4; mi++)
            ldmatrix_x4(af[0][mi][0], af[0][mi][1], af[0][mi][2], af[0][mi][3],
                        dA + SWZ((aRowOff + mi * 16) * 128 + aColOff * 2));
#pragma unroll
        for (int ni = 0; ni < 8; ni++)
            ldmatrix_x2(bf[0][ni][0], bf[0][ni][1],
                        dB + SWZ((bRowOff + ni * 8) * 128 + bColOff * 2));

#pragma unroll
        for (int ks = 0; ks < 4; ks++) {
            int cur = ks & 1, nxt = cur ^ 1;
            if (ks < 3) {   // prefetch next k-step under current HMMAs
#pragma unroll
                for (int mi = 0; mi < 4; mi++)
                    ldmatrix_x4(af[nxt][mi][0], af[nxt][mi][1], af[nxt][mi][2], af[nxt][mi][3],
                                dA + SWZ((aRowOff + mi * 16) * 128 + ((ks + 1) * 16 + aColOff) * 2));
#pragma unroll
                for (int ni = 0; ni < 8; ni++)
                    ldmatrix_x2(bf[nxt][ni][0], bf[nxt][ni][1],
                                dB + SWZ((bRowOff + ni * 8) * 128 + ((ks + 1) * 16 + bColOff) * 2));
            }
#pragma unroll
            for (int mi = 0; mi < 4; mi++)
#pragma unroll
                for (int ni = 0; ni < 8; ni++)
                    mma16816(acc[mi][ni], af[cur][mi], bf[cur][ni]);
        }
        __syncthreads();   // all warps done reading stage s before overwrite
        if (c + STAGES < NCHUNK) load_chunk(c + STAGES, s);
        else asm volatile("cp.async.commit_group;" ::: "memory");
    }

    // ---- epilogue: exp(2*sim), row sums (and col sums via symmetry) ----
    int rBase = tm * 128 + rWarp;
    int cBase = tn * 128 + cWarp;
    int sc = ((tm < (NTILE / 2)) == (tn < (NTILE / 2))) ? 0 : 1;

    float rsum[4][2];
    float csum[8][2];
#pragma unroll
    for (int i = 0; i < 4; i++) { rsum[i][0] = rsum[i][1] = 0.f; }
#pragma unroll
    for (int i = 0; i < 8; i++) { csum[i][0] = csum[i][1] = 0.f; }

#pragma unroll
    for (int mi = 0; mi < 4; mi++) {
        int grow0 = rBase + mi * 16 + (lane >> 2);
        int grow1 = grow0 + 8;
#pragma unroll
        for (int ni = 0; ni < 8; ni++) {
            int gc = cBase + ni * 8 + 2 * (lane & 3);
            float e0 = __expf(2.f * acc[mi][ni][0]);
            float e1 = __expf(2.f * acc[mi][ni][1]);
            float e2 = __expf(2.f * acc[mi][ni][2]);
            float e3 = __expf(2.f * acc[mi][ni][3]);
            if (diag) {
                if (grow0 == gc)     e0 = 0.f;
                if (grow0 == gc + 1) e1 = 0.f;
                if (grow1 == gc)     e2 = 0.f;
                if (grow1 == gc + 1) e3 = 0.f;
            }
            rsum[mi][0] += e0 + e1;
            rsum[mi][1] += e2 + e3;
            csum[ni][0] += e0 + e2;
            csum[ni][1] += e1 + e3;
        }
    }

    // row sums: reduce across lanes sharing a row (lane&3 varies -> xor 1,2)
#pragma unroll
    for (int mi = 0; mi < 4; mi++) {
#pragma unroll
        for (int j = 0; j < 2; j++) {
            float v = rsum[mi][j];
            v += __shfl_xor_sync(0xffffffffu, v, 1);
            v += __shfl_xor_sync(0xffffffffu, v, 2);
            if ((lane & 3) == 0) {
                int grow = rBase + mi * 16 + (lane >> 2) + j * 8;
                atomicAdd(&g_S[sc][f][grow], v);
            }
        }
    }

    // col sums (symmetric contribution) only for off-diagonal tiles:
    if (!diag) {
#pragma unroll
        for (int ni = 0; ni < 8; ni++) {
#pragma unroll
            for (int j = 0; j < 2; j++) {
                float v = csum[ni][j];
                v += __shfl_xor_sync(0xffffffffu, v, 4);
                v += __shfl_xor_sync(0xffffffffu, v, 8);
                v += __shfl_xor_sync(0xffffffffu, v, 16);
                if (lane < 4) {
                    int gc = cBase + ni * 8 + 2 * lane + j;
                    atomicAdd(&g_S[sc][f][gc], v);
                }
            }
        }
    }
}

// ---------------- kernel 4: final loss reduction (1024 thr, 16 independent elems each) ----
__global__ void loss_kernel(float* __restrict__ out) {
    __shared__ float ws[32];
    int t = threadIdx.x;
    float nom[16], cr[16];
#pragma unroll
    for (int i = 0; i < 16; i++) {
        int idx = t + i * 1024;
        int f = idx >> 13, r = idx & (BATCH - 1);
        nom[i] = g_S[0][f][r];
        cr[i]  = g_S[1][f][r];
    }
    float p = 0.f;
#pragma unroll
    for (int i = 0; i < 16; i++)
        p += -logf(nom[i] / (nom[i] + cr[i]) + 1e-8f);
#pragma unroll
    for (int o = 16; o; o >>= 1) p += __shfl_xor_sync(0xffffffffu, p, o);
    if ((t & 31) == 0) ws[t >> 5] = p;
    __syncthreads();
    if (t == 0) {
        float a = 0.f;
#pragma unroll
        for (int w = 0; w < 32; w++) a += ws[w];
        out[0] = a * (1.0f / HALF_B);
    }
}

// ---------------- launch ----------------
extern "C" void kernel_launch(void* const* d_in, const int* in_sizes, int n_in,
                              void* d_out, int out_size) {
    const float* text  = (const float*)d_in[0];
    const float* image = (const float*)d_in[1];
    const int*   label = (const int*)d_in[2];

    void* sAddr = nullptr;
    cudaGetSymbolAddress(&sAddr, g_S);
    cudaMemsetAsync(sAddr, 0, sizeof(float) * 2 * 2 * BATCH);   // launch idx 0

    perm_kernel<<<1, 1024>>>(label);                            // idx 1
    norm_kernel<<<dim3(BATCH, 2), 256>>>(text, image);          // idx 2
    dummy_kernel<<<1, 32>>>();                                  // idx 3

    cudaFuncSetAttribute(gram_kernel, cudaFuncAttributeMaxDynamicSharedMemorySize, SMEM_DYN);
    gram_kernel<<<dim3(NPAIR, 2), 128, SMEM_DYN>>>();           // idx 4  (ncu window)

    loss_kernel<<<1, 1024>>>((float*)d_out);                    // idx 5
}

// round 9
// speedup vs baseline: 1.4183x; 1.0218x over previous
#include <cuda_runtime.h>
#include <cuda_bf16.h>
#include <cstdint>

#define BATCH   8192
#define DIM     1024
#define HALF_B  4096

// ---------------- device scratch (static, no runtime alloc) ----------------
__device__ __nv_bfloat16 g_P[2][BATCH][DIM];   // permuted, normalized, bf16 (32 MB)
__device__ int   g_perm[BATCH];
__device__ float g_S[2][2][BATCH];             // [same=0/cross=1][feature][row]

// ---------------- helpers ----------------
__device__ __forceinline__ uint32_t smem_u32(const void* p) {
    uint32_t a;
    asm("{ .reg .u64 t; cvta.to.shared.u64 t, %1; cvt.u32.u64 %0, t; }" : "=r"(a) : "l"(p));
    return a;
}
__device__ __forceinline__ void cpa16(uint32_t s, const void* g) {
    asm volatile("cp.async.cg.shared.global [%0], [%1], 16;" :: "r"(s), "l"(g) : "memory");
}
#define SWZ(o) ((o) ^ (((o) >> 3) & 0x70))

__device__ __forceinline__ void ldmatrix_x4(uint32_t& r0, uint32_t& r1, uint32_t& r2, uint32_t& r3,
                                            uint32_t addr) {
    asm volatile("ldmatrix.sync.aligned.m8n8.x4.shared.b16 {%0,%1,%2,%3}, [%4];"
                 : "=r"(r0), "=r"(r1), "=r"(r2), "=r"(r3) : "r"(addr));
}
__device__ __forceinline__ void ldmatrix_x2(uint32_t& r0, uint32_t& r1, uint32_t addr) {
    asm volatile("ldmatrix.sync.aligned.m8n8.x2.shared.b16 {%0,%1}, [%2];"
                 : "=r"(r0), "=r"(r1) : "r"(addr));
}
__device__ __forceinline__ void mma16816(float* c, const uint32_t* a, const uint32_t* b) {
    asm volatile("mma.sync.aligned.m16n8k16.row.col.f32.bf16.bf16.f32 "
                 "{%0,%1,%2,%3}, {%4,%5,%6,%7}, {%8,%9}, {%0,%1,%2,%3};"
                 : "+f"(c[0]), "+f"(c[1]), "+f"(c[2]), "+f"(c[3])
                 : "r"(a[0]), "r"(a[1]), "r"(a[2]), "r"(a[3]), "r"(b[0]), "r"(b[1]));
}

// ---------------- kernel 1: permutation (stable partition by label) ----------------
__global__ void perm_kernel(const int* __restrict__ label) {
    __shared__ int wsum[32];
    int t = threadIdx.x;
    int l[8]; int c = 0;
#pragma unroll
    for (int i = 0; i < 8; i++) { l[i] = label[t * 8 + i]; c += l[i]; }
    int v = c, lane = t & 31, w = t >> 5;
#pragma unroll
    for (int o = 1; o < 32; o <<= 1) {
        int n = __shfl_up_sync(0xffffffffu, v, o);
        if (lane >= o) v += n;
    }
    if (lane == 31) wsum[w] = v;
    __syncthreads();
    if (w == 0) {
        int x = wsum[lane];
#pragma unroll
        for (int o = 1; o < 32; o <<= 1) {
            int n = __shfl_up_sync(0xffffffffu, x, o);
            if (lane >= o) x += n;
        }
        wsum[lane] = x;
    }
    __syncthreads();
    int run = v - c + (w ? wsum[w - 1] : 0);   // ones strictly before t*8
#pragma unroll
    for (int i = 0; i < 8; i++) {
        int idx = t * 8 + i;
        g_perm[idx] = l[i] ? run : (HALF_B + (idx - run));
        run += l[i];
    }
}

// ---------------- kernel 2: normalize + scatter to bf16 ----------------
__global__ void norm_kernel(const float* __restrict__ text, const float* __restrict__ image) {
    int f = blockIdx.y;
    int row = blockIdx.x;
    int t = threadIdx.x;
    const float4* src = (const float4*)((f == 0 ? text : image) + (size_t)row * DIM);
    float4 v = src[t];
    float s = v.x * v.x + v.y * v.y + v.z * v.z + v.w * v.w;
#pragma unroll
    for (int o = 16; o; o >>= 1) s += __shfl_xor_sync(0xffffffffu, s, o);
    __shared__ float ws[8];
    __shared__ float s_inv;
    if ((t & 31) == 0) ws[t >> 5] = s;
    __syncthreads();
    if (t == 0) {
        float a = 0.f;
#pragma unroll
        for (int wq = 0; wq < 8; wq++) a += ws[wq];
        s_inv = 1.0f / fmaxf(sqrtf(a), 1e-12f);
    }
    __syncthreads();
    float inv = s_inv;
    int dest = g_perm[row];
    __nv_bfloat16* dst = &g_P[f][dest][0];
    __nv_bfloat162 a0 = __floats2bfloat162_rn(v.x * inv, v.y * inv);
    __nv_bfloat162 a1 = __floats2bfloat162_rn(v.z * inv, v.w * inv);
    ((__nv_bfloat162*)dst)[2 * t]     = a0;
    ((__nv_bfloat162*)dst)[2 * t + 1] = a1;
}

// ---------------- dummy kernel (aligns ncu capture window onto gram_kernel) --------
__global__ void dummy_kernel() {}

// ---------------- kernel 3: symmetric Gram GEMM (HMMA) + fused exp-sum epilogue ----
// 128x128 tile per CTA, only lower-triangular tile pairs (tm >= tn).
// 128 threads = 4 warps; warp tile 64x64. 2 CTAs/SM.
// Single __syncthreads per K-chunk; fragment double-buffering; XOR-folded
// swizzled addresses (addr(ks) = base ^ (32*ks)).
constexpr int NCHUNK = DIM / 64, STAGES = 3;
constexpr int STAGE_A = 128 * 128;          // 16 KB (128 rows x 64 bf16)
constexpr int STAGE_BYTES = 2 * STAGE_A;    // 32 KB (A + B)
constexpr int SMEM_DYN = STAGES * STAGE_BYTES;   // 96 KB
constexpr int NTILE = BATCH / 128;          // 64
constexpr int NPAIR = NTILE * (NTILE + 1) / 2;   // 2080

__global__ void __launch_bounds__(128, 2) gram_kernel() {
    extern __shared__ __align__(1024) char smem_raw[];
    uint32_t sb = smem_u32(smem_raw);
    int tid = threadIdx.x, lane = tid & 31, wid = tid >> 5;
    int p = blockIdx.x, f = blockIdx.y;

    // triangular decode: tm >= tn
    int tm = (int)((sqrtf(8.f * (float)p + 1.f) - 1.f) * 0.5f);
    while ((tm + 1) * (tm + 2) / 2 <= p) tm++;
    while (tm * (tm + 1) / 2 > p) tm--;
    int tn = p - tm * (tm + 1) / 2;
    bool diag = (tm == tn);

    const char* baseA = (const char*)&g_P[f][tm * 128][0];
    const char* baseB = (const char*)&g_P[f][tn * 128][0];

    auto load_chunk = [&](int c, int s) {
        uint32_t dA = sb + s * STAGE_BYTES;
        uint32_t dB = dA + STAGE_A;
        const char* gA = baseA + c * 128;
        const char* gB = baseB + c * 128;
#pragma unroll
        for (int i = 0; i < 8; i++) {       // A: 128 rows x 8 segs = 1024 cp / 128 thr
            int o = tid + (i << 7); int r = o >> 3, sg = o & 7;
            cpa16(dA + SWZ(r * 128 + sg * 16), gA + (size_t)r * 2048 + sg * 16);
        }
#pragma unroll
        for (int i = 0; i < 8; i++) {
            int o = tid + (i << 7); int r = o >> 3, sg = o & 7;
            cpa16(dB + SWZ(r * 128 + sg * 16), gB + (size_t)r * 2048 + sg * 16);
        }
        asm volatile("cp.async.commit_group;" ::: "memory");
    };

    // prologue: 2 chunks in flight
    load_chunk(0, 0);
    load_chunk(1, 1);

    int wm = wid & 1, wn = wid >> 1;
    int rWarp = wm * 64;            // warp's M offset within tile
    int cWarp = wn * 64;            // warp's N offset within tile
    int quad = lane >> 3, laneRow = lane & 7;
    int aRowOff = rWarp + (quad & 1) * 8 + laneRow;   // + mi*16
    int aColOff = (quad >> 1) * 8;                    // + ks*16 cols
    int bRowOff = cWarp + laneRow;                    // + ni*8
    int bColOff = ((lane >> 3) & 1) * 8;              // + ks*16 cols

    // swizzled fragment base offsets (ks=0); addr(ks) = base ^ (32*ks)
    uint32_t aB[4], bB[8];
#pragma unroll
    for (int mi = 0; mi < 4; mi++)
        aB[mi] = SWZ((uint32_t)((aRowOff + mi * 16) * 128 + aColOff * 2));
#pragma unroll
    for (int ni = 0; ni < 8; ni++)
        bB[ni] = SWZ((uint32_t)((bRowOff + ni * 8) * 128 + bColOff * 2));

    float acc[4][8][4];
#pragma unroll
    for (int mi = 0; mi < 4; mi++)
#pragma unroll
        for (int ni = 0; ni < 8; ni++)
#pragma unroll
            for (int j = 0; j < 4; j++) acc[mi][ni][j] = 0.f;

    uint32_t af[2][4][4], bf[2][8][2];

    for (int c = 0; c < NCHUNK; c++) {
        int s = c % STAGES;
        asm volatile("cp.async.wait_group 1;" ::: "memory");
        __syncthreads();   // chunk c visible everywhere; stage (c-1)%3 reads all done
        if (c + 2 < NCHUNK) load_chunk(c + 2, (c + 2) % STAGES);
        else asm volatile("cp.async.commit_group;" ::: "memory");

        uint32_t dA = sb + s * STAGE_BYTES;
        uint32_t dB = dA + STAGE_A;

        // prime k-step 0 fragments
#pragma unroll
        for (int mi = 0; mi < 4; mi++)
            ldmatrix_x4(af[0][mi][0], af[0][mi][1], af[0][mi][2], af[0][mi][3], dA + aB[mi]);
#pragma unroll
        for (int ni = 0; ni < 8; ni++)
            ldmatrix_x2(bf[0][ni][0], bf[0][ni][1], dB + bB[ni]);

#pragma unroll
        for (int ks = 0; ks < 4; ks++) {
            int cur = ks & 1, nxt = cur ^ 1;
            if (ks < 3) {   // prefetch next k-step under current HMMAs
                uint32_t kx = (uint32_t)((ks + 1) << 5);
#pragma unroll
                for (int mi = 0; mi < 4; mi++)
                    ldmatrix_x4(af[nxt][mi][0], af[nxt][mi][1], af[nxt][mi][2], af[nxt][mi][3],
                                dA + (aB[mi] ^ kx));
#pragma unroll
                for (int ni = 0; ni < 8; ni++)
                    ldmatrix_x2(bf[nxt][ni][0], bf[nxt][ni][1], dB + (bB[ni] ^ kx));
            }
#pragma unroll
            for (int mi = 0; mi < 4; mi++)
#pragma unroll
                for (int ni = 0; ni < 8; ni++)
                    mma16816(acc[mi][ni], af[cur][mi], bf[cur][ni]);
        }
    }

    // ---- epilogue: exp(2*sim), row sums (and col sums via symmetry) ----
    int rBase = tm * 128 + rWarp;
    int cBase = tn * 128 + cWarp;
    int sc = ((tm < (NTILE / 2)) == (tn < (NTILE / 2))) ? 0 : 1;

    float rsum[4][2];
    float csum[8][2];
#pragma unroll
    for (int i = 0; i < 4; i++) { rsum[i][0] = rsum[i][1] = 0.f; }
#pragma unroll
    for (int i = 0; i < 8; i++) { csum[i][0] = csum[i][1] = 0.f; }

#pragma unroll
    for (int mi = 0; mi < 4; mi++) {
        int grow0 = rBase + mi * 16 + (lane >> 2);
        int grow1 = grow0 + 8;
#pragma unroll
        for (int ni = 0; ni < 8; ni++) {
            int gc = cBase + ni * 8 + 2 * (lane & 3);
            float e0 = __expf(2.f * acc[mi][ni][0]);
            float e1 = __expf(2.f * acc[mi][ni][1]);
            float e2 = __expf(2.f * acc[mi][ni][2]);
            float e3 = __expf(2.f * acc[mi][ni][3]);
            if (diag) {
                if (grow0 == gc)     e0 = 0.f;
                if (grow0 == gc + 1) e1 = 0.f;
                if (grow1 == gc)     e2 = 0.f;
                if (grow1 == gc + 1) e3 = 0.f;
            }
            rsum[mi][0] += e0 + e1;
            rsum[mi][1] += e2 + e3;
            csum[ni][0] += e0 + e2;
            csum[ni][1] += e1 + e3;
        }
    }

    // row sums: reduce across lanes sharing a row (lane&3 varies -> xor 1,2)
#pragma unroll
    for (int mi = 0; mi < 4; mi++) {
#pragma unroll
        for (int j = 0; j < 2; j++) {
            float v = rsum[mi][j];
            v += __shfl_xor_sync(0xffffffffu, v, 1);
            v += __shfl_xor_sync(0xffffffffu, v, 2);
            if ((lane & 3) == 0) {
                int grow = rBase + mi * 16 + (lane >> 2) + j * 8;
                atomicAdd(&g_S[sc][f][grow], v);
            }
        }
    }

    // col sums (symmetric contribution) only for off-diagonal tiles:
    if (!diag) {
#pragma unroll
        for (int ni = 0; ni < 8; ni++) {
#pragma unroll
            for (int j = 0; j < 2; j++) {
                float v = csum[ni][j];
                v += __shfl_xor_sync(0xffffffffu, v, 4);
                v += __shfl_xor_sync(0xffffffffu, v, 8);
                v += __shfl_xor_sync(0xffffffffu, v, 16);
                if (lane < 4) {
                    int gc = cBase + ni * 8 + 2 * lane + j;
                    atomicAdd(&g_S[sc][f][gc], v);
                }
            }
        }
    }
}

// ---------------- kernel 4: final loss reduction (1024 thr, 16 independent elems each) ----
__global__ void loss_kernel(float* __restrict__ out) {
    __shared__ float ws[32];
    int t = threadIdx.x;
    float nom[16], cr[16];
#pragma unroll
    for (int i = 0; i < 16; i++) {
        int idx = t + i * 1024;
        int f = idx >> 13, r = idx & (BATCH - 1);
        nom[i] = g_S[0][f][r];
        cr[i]  = g_S[1][f][r];
    }
    float p = 0.f;
#pragma unroll
    for (int i = 0; i < 16; i++)
        p += -logf(nom[i] / (nom[i] + cr[i]) + 1e-8f);
#pragma unroll
    for (int o = 16; o; o >>= 1) p += __shfl_xor_sync(0xffffffffu, p, o);
    if ((t & 31) == 0) ws[t >> 5] = p;
    __syncthreads();
    if (t == 0) {
        float a = 0.f;
#pragma unroll
        for (int w = 0; w < 32; w++) a += ws[w];
        out[0] = a * (1.0f / HALF_B);
    }
}

// ---------------- launch ----------------
extern "C" void kernel_launch(void* const* d_in, const int* in_sizes, int n_in,
                              void* d_out, int out_size) {
    const float* text  = (const float*)d_in[0];
    const float* image = (const float*)d_in[1];
    const int*   label = (const int*)d_in[2];

    void* sAddr = nullptr;
    cudaGetSymbolAddress(&sAddr, g_S);
    cudaMemsetAsync(sAddr, 0, sizeof(float) * 2 * 2 * BATCH);   // launch idx 0

    perm_kernel<<<1, 1024>>>(label);                            // idx 1
    norm_kernel<<<dim3(BATCH, 2), 256>>>(text, image);          // idx 2
    dummy_kernel<<<1, 32>>>();                                  // idx 3

    cudaFuncSetAttribute(gram_kernel, cudaFuncAttributeMaxDynamicSharedMemorySize, SMEM_DYN);
    gram_kernel<<<dim3(NPAIR, 2), 128, SMEM_DYN>>>();           // idx 4  (ncu window)

    loss_kernel<<<1, 1024>>>((float*)d_out);                    // idx 5
}